// round 8
// baseline (speedup 1.0000x reference)
#include <cuda_runtime.h>

// Problem constants: B=32, S1=14, S2=14, NC=2, DC=16, F=32, I=8
#define NROWS   200704      // B*S1*S2*NC*DC
#define DE      32          // NC*DC (weights repeat with row period 32)
#define HALF    51380224    // NROWS * F * I (elements per output tensor)
#define JMAX    6272        // rows per de  (NROWS / 32)
#define GRID    740         // 148 SMs * 5 blocks  -> exactly one wave at 48 regs
#define WSTRIDE 185         // (GRID*8 warps) / 32 de values

__device__ __forceinline__ float ex2a(float x) {
    float y; asm("ex2.approx.ftz.f32 %0, %1;" : "=f"(y) : "f"(x)); return y;
}
__device__ __forceinline__ float rcpa(float x) {
    float y; asm("rcp.approx.ftz.f32 %0, %1;" : "=f"(y) : "f"(x)); return y;
}

// Lane layout (R2): lane owns f_lo = lane>>1 and f_hi = f_lo+16, with the 4
// consecutive i's (lane&1)*4.. +3 as a float4. Every global access is a fully
// coalesced 512B STG.128/LDG.128. Persistent mapping: warp wg keeps de = wg&31
// for its whole life and stride-loops rows j = (wg>>5), +185, ... < 6272, so
// weights + the exact max_f(Wt) butterfly are paid once per ~34 rows.
__global__ void __launch_bounds__(256)
mhsa_main(const float* __restrict__ U,
          const float* __restrict__ Wt,
          const float* __restrict__ Wa,
          float* __restrict__ outC,
          float* __restrict__ outUI)
{
    const int wg   = blockIdx.x * 8 + (threadIdx.x >> 5);
    const int lane = threadIdx.x & 31;
    const int de   = wg & (DE - 1);
    const int wr   = wg >> 5;              // 0..184

    // ---- weights, once per warp (L1-resident)
    const float4* wa4 = (const float4*)(Wa + de * 256);
    const float4* wt4 = (const float4*)(Wt + de * 256);
    const float4 waL = wa4[lane];
    const float4 waH = wa4[lane + 32];
    const float4 wtL = wt4[lane];
    const float4 wtH = wt4[lane + 32];

    // ---- exact mw[i] = max_f Wt[de,f,i], once per warp (parity butterfly)
    float4 wm;
    wm.x = fmaxf(wtL.x, wtH.x);
    wm.y = fmaxf(wtL.y, wtH.y);
    wm.z = fmaxf(wtL.z, wtH.z);
    wm.w = fmaxf(wtL.w, wtH.w);
    #pragma unroll
    for (int m = 2; m <= 16; m <<= 1) {
        wm.x = fmaxf(wm.x, __shfl_xor_sync(0xffffffffu, wm.x, m));
        wm.y = fmaxf(wm.y, __shfl_xor_sync(0xffffffffu, wm.y, m));
        wm.z = fmaxf(wm.z, __shfl_xor_sync(0xffffffffu, wm.z, m));
        wm.w = fmaxf(wm.w, __shfl_xor_sync(0xffffffffu, wm.w, m));
    }

    const int f_lo = lane >> 1;
    const float SC = 0.25f * 1.4426950408889634f;   // fold /sqrt(16) and log2e

    // ---- persistent row loop with one-ahead U prefetch
    int j = wr;
    float u_cur = (j < JMAX) ? U[(de + (j << 5)) * 32 + lane] : 0.0f;

    while (j < JMAX) {
        const int jn = j + WSTRIDE;
        const float u_next = (jn < JMAX) ? U[(de + (jn << 5)) * 32 + lane] : 0.0f;

        const int row = de + (j << 5);

        // lane l holds U[row, f=l]; grab this lane's two f's
        const float u_lo = __shfl_sync(0xffffffffu, u_cur, f_lo);
        const float u_hi = __shfl_sync(0xffffffffu, u_cur, f_lo + 16);

        // ---- U_hat_I = u * W_affine
        float4 uiL, uiH;
        uiL.x = u_lo * waL.x; uiL.y = u_lo * waL.y; uiL.z = u_lo * waL.z; uiL.w = u_lo * waL.w;
        uiH.x = u_hi * waH.x; uiH.y = u_hi * waH.y; uiH.z = u_hi * waH.z; uiH.w = u_hi * waH.w;

        float4* oUI = (float4*)(outUI + (size_t)row * 256);
        oUI[lane]      = uiL;
        oUI[lane + 32] = uiH;

        // ---- diag[i] = sum_f ui^2 / 4  (parity butterfly)
        float4 sq;
        sq.x = fmaf(uiL.x, uiL.x, uiH.x * uiH.x);
        sq.y = fmaf(uiL.y, uiL.y, uiH.y * uiH.y);
        sq.z = fmaf(uiL.z, uiL.z, uiH.z * uiH.z);
        sq.w = fmaf(uiL.w, uiL.w, uiH.w * uiH.w);
        #pragma unroll
        for (int m = 2; m <= 16; m <<= 1) {
            sq.x += __shfl_xor_sync(0xffffffffu, sq.x, m);
            sq.y += __shfl_xor_sync(0xffffffffu, sq.y, m);
            sq.z += __shfl_xor_sync(0xffffffffu, sq.z, m);
            sq.w += __shfl_xor_sync(0xffffffffu, sq.w, m);
        }

        // ds = diag*log2e; diag >= 0 so the exact row max of ds*wt = ds*wm
        float4 ds, mx;
        ds.x = sq.x * SC; ds.y = sq.y * SC; ds.z = sq.z * SC; ds.w = sq.w * SC;
        mx.x = ds.x * wm.x; mx.y = ds.y * wm.y; mx.z = ds.z * wm.z; mx.w = ds.w * wm.w;

        float4 eL, eH;
        eL.x = ex2a(fmaf(ds.x, wtL.x, -mx.x));
        eL.y = ex2a(fmaf(ds.y, wtL.y, -mx.y));
        eL.z = ex2a(fmaf(ds.z, wtL.z, -mx.z));
        eL.w = ex2a(fmaf(ds.w, wtL.w, -mx.w));
        eH.x = ex2a(fmaf(ds.x, wtH.x, -mx.x));
        eH.y = ex2a(fmaf(ds.y, wtH.y, -mx.y));
        eH.z = ex2a(fmaf(ds.z, wtH.z, -mx.z));
        eH.w = ex2a(fmaf(ds.w, wtH.w, -mx.w));

        float4 s;
        s.x = eL.x + eH.x; s.y = eL.y + eH.y; s.z = eL.z + eH.z; s.w = eL.w + eH.w;
        #pragma unroll
        for (int m = 2; m <= 16; m <<= 1) {
            s.x += __shfl_xor_sync(0xffffffffu, s.x, m);
            s.y += __shfl_xor_sync(0xffffffffu, s.y, m);
            s.z += __shfl_xor_sync(0xffffffffu, s.z, m);
            s.w += __shfl_xor_sync(0xffffffffu, s.w, m);
        }

        float4 inv;
        inv.x = rcpa(s.x); inv.y = rcpa(s.y); inv.z = rcpa(s.z); inv.w = rcpa(s.w);

        float4 cL, cH;
        cL.x = eL.x * inv.x; cL.y = eL.y * inv.y; cL.z = eL.z * inv.z; cL.w = eL.w * inv.w;
        cH.x = eH.x * inv.x; cH.y = eH.y * inv.y; cH.z = eH.z * inv.z; cH.w = eH.w * inv.w;

        float4* oC = (float4*)(outC + (size_t)row * 256);
        oC[lane]      = cL;
        oC[lane + 32] = cH;

        j = jn;
        u_cur = u_next;
    }
}

extern "C" void kernel_launch(void* const* d_in, const int* in_sizes, int n_in,
                              void* d_out, int out_size)
{
    const float* U  = (const float*)d_in[0];   // U_hat    (6,422,528)
    const float* Wt = (const float*)d_in[1];   // W_t      (8,192)
    const float* Wa = (const float*)d_in[2];   // W_affine (8,192)
    float* outC  = (float*)d_out;              // C first (return order)
    float* outUI = (float*)d_out + HALF;       // then U_hat_I

    mhsa_main<<<GRID, 256>>>(U, Wt, Wa, outC, outUI);
}